// round 10
// baseline (speedup 1.0000x reference)
#include <cuda_runtime.h>
#include <cuda_fp16.h>
#include <math.h>
#include <stdint.h>

#define T_DIM 4096
#define C_DIM 768
#define H_DIM 12
#define D_DIM 64
#define C3_DIM 2304

// ---------------------------------------------------------------------------
// Global scratch (allocation-free rule). 16B-aligned for uint4/cp.async.
// ---------------------------------------------------------------------------
__device__ __align__(16) __half g_qh[H_DIM * T_DIM * D_DIM];
__device__ __align__(16) __half g_kh[H_DIM * T_DIM * D_DIM];
__device__ __align__(16) __half g_vh[H_DIM * T_DIM * D_DIM];
__device__ __align__(16) __half g_xh[T_DIM * C_DIM];
__device__ __align__(16) __half g_yh[T_DIM * C_DIM];
__device__ __align__(16) __half g_wq[C_DIM * C3_DIM];    // W_qkv fp16 [K][N]
__device__ __align__(16) __half g_wp[C_DIM * C_DIM];     // W_proj fp16 [K][N]

// ---------------------------------------------------------------------------
// PTX helpers (sm_80-level: compile under plain sm_103 target)
// ---------------------------------------------------------------------------
__device__ __forceinline__ uint32_t smem_u32(const void* p) {
    uint32_t a;
    asm("{ .reg .u64 t; cvta.to.shared.u64 t, %1; cvt.u32.u64 %0, t; }"
        : "=r"(a) : "l"(p));
    return a;
}

#define CP16(dst, src) \
    asm volatile("cp.async.cg.shared.global [%0], [%1], 16;" \
                 :: "r"(dst), "l"(src))
#define CP_COMMIT() asm volatile("cp.async.commit_group;" ::: "memory")
#define CP_WAIT0()  asm volatile("cp.async.wait_group 0;" ::: "memory")
#define CP_WAIT1()  asm volatile("cp.async.wait_group 1;" ::: "memory")

#define LDSM_X4(r0, r1, r2, r3, addr) \
    asm volatile("ldmatrix.sync.aligned.m8n8.x4.shared.b16 {%0,%1,%2,%3}, [%4];" \
                 : "=r"(r0), "=r"(r1), "=r"(r2), "=r"(r3) : "r"(addr))

#define LDSM_X4T(r0, r1, r2, r3, addr) \
    asm volatile("ldmatrix.sync.aligned.m8n8.x4.trans.shared.b16 {%0,%1,%2,%3}, [%4];" \
                 : "=r"(r0), "=r"(r1), "=r"(r2), "=r"(r3) : "r"(addr))

#define MMA16816(d, a, b0, b1) \
    asm volatile("mma.sync.aligned.m16n8k16.row.col.f32.f16.f16.f32 " \
                 "{%0,%1,%2,%3}, {%4,%5,%6,%7}, {%8,%9}, {%0,%1,%2,%3};" \
                 : "+f"((d)[0]), "+f"((d)[1]), "+f"((d)[2]), "+f"((d)[3]) \
                 : "r"((a)[0]), "r"((a)[1]), "r"((a)[2]), "r"((a)[3]), \
                   "r"(b0), "r"(b1))

__device__ __forceinline__ uint32_t packh2(float lo, float hi) {
    uint32_t d;
    asm("cvt.rn.f16x2.f32 %0, %1, %2;" : "=r"(d) : "f"(hi), "f"(lo));
    return d;
}
__device__ __forceinline__ uint32_t ex2h2(uint32_t a) {
    uint32_t d;
    asm("ex2.approx.f16x2 %0, %1;" : "=r"(d) : "r"(a));
    return d;
}
__device__ __forceinline__ float ex2(float x) {
    float y;
    asm("ex2.approx.ftz.f32 %0, %1;" : "=f"(y) : "f"(x));
    return y;
}

// ---------------------------------------------------------------------------
// Prepass: fp32 -> fp16 (same layout)
// ---------------------------------------------------------------------------
__global__ void convert_f16_kernel(const float* __restrict__ src,
                                   __half* __restrict__ dst, int n4) {
    int i = blockIdx.x * blockDim.x + threadIdx.x;
    if (i >= n4) return;
    float4 v = ((const float4*)src)[i];
    uint2 o;
    o.x = packh2(v.x, v.y);
    o.y = packh2(v.z, v.w);
    *(uint2*)&dst[4 * (size_t)i] = o;
}

// ---------------------------------------------------------------------------
// fp16 mma GEMM, 3-stage cp.async pipeline. C = A[M,K] @ B[K,N] (B row-major).
// Tile 128x128, BK=64, 8 warps (64x32 each).
// MODE 0: qkv scatter (Q pre-scaled by 0.125*log2e). MODE 1: fp32 out.
// ---------------------------------------------------------------------------
#define GA_BUF (128 * 72)               // halves per A stage
#define GB_BUF (64 * 136)               // halves per B stage
#define GA_BUF_B (GA_BUF * 2)
#define GB_BUF_B (GB_BUF * 2)
#define GEMM_SMEM_BYTES (3 * (GA_BUF + GB_BUF) * 2)

#define Q_SCALE 0.18033688011112042f    // 0.125 * log2(e)

template <int MODE>
__global__ __launch_bounds__(256, 2)
void mma_gemm_kernel(const __half* __restrict__ A,
                     const __half* __restrict__ B, int ldb,
                     const float* __restrict__ bias,
                     float* __restrict__ outp) {
    extern __shared__ __half sm[];
    __half (*As)[128][72] = (__half(*)[128][72])sm;
    __half (*Bs)[64][136] = (__half(*)[64][136])(sm + 3 * GA_BUF);

    const int tid = threadIdx.x;
    const int w = tid >> 5, lane = tid & 31;
    const int wm = w >> 2, wn = w & 3;
    const int g = lane >> 2, qd = lane & 3;
    const int m0 = blockIdx.y * 128;
    const int n0 = blockIdx.x * 128;

    float acc[4][4][4];
    #pragma unroll
    for (int mt = 0; mt < 4; mt++)
        #pragma unroll
        for (int nt = 0; nt < 4; nt++)
            #pragma unroll
            for (int r = 0; r < 4; r++) acc[mt][nt][r] = 0.0f;

    // prologue: stage chunks 0 and 1 as separate groups
    #pragma unroll
    for (int pc = 0; pc < 2; pc++) {
        const int k0 = pc * 64;
        #pragma unroll
        for (int i = tid; i < 1024; i += 256) {
            const int ra = i >> 3, sga = i & 7;
            CP16(smem_u32(&As[pc][ra][sga * 8]),
                 &A[(size_t)(m0 + ra) * C_DIM + k0 + sga * 8]);
            const int rb = i >> 4, sgb = i & 15;
            CP16(smem_u32(&Bs[pc][rb][sgb * 8]),
                 &B[(size_t)(k0 + rb) * ldb + n0 + sgb * 8]);
        }
        CP_COMMIT();
    }

    uint32_t a_base[4];
    #pragma unroll
    for (int mt = 0; mt < 4; mt++)
        a_base[mt] = smem_u32(&As[0][wm * 64 + mt * 16 + (lane & 15)][(lane >> 4) * 8]);
    const uint32_t b_base = smem_u32(&Bs[0][lane & 15][wn * 32 + (lane >> 4) * 8]);

    for (int c = 0; c < 12; c++) {
        if (c < 11) { CP_WAIT1(); } else { CP_WAIT0(); }
        __syncthreads();
        if (c + 2 < 12) {
            const int k0 = (c + 2) * 64;
            const int nb = (c + 2) % 3;
            #pragma unroll
            for (int i = tid; i < 1024; i += 256) {
                const int ra = i >> 3, sga = i & 7;
                CP16(smem_u32(&As[nb][ra][sga * 8]),
                     &A[(size_t)(m0 + ra) * C_DIM + k0 + sga * 8]);
                const int rb = i >> 4, sgb = i & 15;
                CP16(smem_u32(&Bs[nb][rb][sgb * 8]),
                     &B[(size_t)(k0 + rb) * ldb + n0 + sgb * 8]);
            }
            CP_COMMIT();
        }
        const uint32_t boffA = (uint32_t)(c % 3) * GA_BUF_B;
        const uint32_t boffB = (uint32_t)(c % 3) * GB_BUF_B;
        #pragma unroll
        for (int kt = 0; kt < 4; kt++) {
            uint32_t af[4][4];
            #pragma unroll
            for (int mt = 0; mt < 4; mt++)
                LDSM_X4(af[mt][0], af[mt][1], af[mt][2], af[mt][3],
                        a_base[mt] + boffA + kt * 32);
            #pragma unroll
            for (int p = 0; p < 2; p++) {
                uint32_t b0, b1, b2, b3;
                LDSM_X4T(b0, b1, b2, b3,
                         b_base + boffB + kt * (16 * 272) + p * 32);
                #pragma unroll
                for (int mt = 0; mt < 4; mt++) {
                    MMA16816(acc[mt][2 * p], af[mt], b0, b1);
                    MMA16816(acc[mt][2 * p + 1], af[mt], b2, b3);
                }
            }
        }
    }

    // epilogue
    #pragma unroll
    for (int nt = 0; nt < 4; nt++) {
        const int f = n0 + wn * 32 + nt * 8 + qd * 2;
        const float b0v = bias[f], b1v = bias[f + 1];
        if (MODE == 0) {
            const int sec = f / C_DIM;
            const int cc = f - sec * C_DIM;
            const int hh = cc >> 6, d = cc & 63;
            const float sc = (sec == 0) ? Q_SCALE : 1.0f;
            __half* dst = (sec == 0) ? g_qh : (sec == 1) ? g_kh : g_vh;
            #pragma unroll
            for (int mt = 0; mt < 4; mt++) {
                const int m = m0 + wm * 64 + mt * 16 + g;
                *(uint32_t*)&dst[((size_t)hh * T_DIM + m) * D_DIM + d] =
                    packh2((acc[mt][nt][0] + b0v) * sc, (acc[mt][nt][1] + b1v) * sc);
                *(uint32_t*)&dst[((size_t)hh * T_DIM + m + 8) * D_DIM + d] =
                    packh2((acc[mt][nt][2] + b0v) * sc, (acc[mt][nt][3] + b1v) * sc);
            }
        } else {
            #pragma unroll
            for (int mt = 0; mt < 4; mt++) {
                const int m = m0 + wm * 64 + mt * 16 + g;
                float2 r0 = make_float2(acc[mt][nt][0] + b0v, acc[mt][nt][1] + b1v);
                float2 r1 = make_float2(acc[mt][nt][2] + b0v, acc[mt][nt][3] + b1v);
                *(float2*)&outp[(size_t)m * C_DIM + f] = r0;
                *(float2*)&outp[(size_t)(m + 8) * C_DIM + f] = r1;
            }
        }
    }
}

// ---------------------------------------------------------------------------
// Causal flash attention, fp16 mma, 3-stage cp.async K/V pipeline.
// CTA: 128 q-rows, 8 warps (16 rows each), key blocks of 64.
// Softmax log2-domain; f32 subtract (precision), f16x2 ex2 -> P fragments;
// row-sum l via ones-column MMA.
// ---------------------------------------------------------------------------
#define KV_BUF (64 * 72)
#define KV_BUF_B (KV_BUF * 2)
#define ATTN_SMEM_BYTES ((128 * 72 + 6 * KV_BUF) * 2)
#define ONES_H2 0x3C003C00u             // (1.0h, 1.0h)

__global__ __launch_bounds__(256, 2)
void attn_kernel() {
    extern __shared__ __half sm[];
    __half (*Qs)[72] = (__half(*)[72])sm;
    __half (*Ks)[64][72] = (__half(*)[64][72])(sm + 128 * 72);
    __half (*Vs)[64][72] = (__half(*)[64][72])(sm + 128 * 72 + 3 * KV_BUF);

    const int h = blockIdx.y;
    const int qb = gridDim.x - 1 - blockIdx.x;   // heavy blocks first
    const int tid = threadIdx.x;
    const int w = tid >> 5, lane = tid & 31;
    const int g = lane >> 2, qd = lane & 3;

    const int jend = 2 * qb + 1;

    // prologue: group 0 = Q + K/V block 0; group 1 = K/V block 1 (jend >= 1)
    const __half* Qg = g_qh + ((size_t)h * T_DIM + qb * 128) * D_DIM;
    #pragma unroll
    for (int i = tid; i < 1024; i += 256) {
        const int r = i >> 3, sg = i & 7;
        CP16(smem_u32(&Qs[r][sg * 8]), &Qg[r * D_DIM + sg * 8]);
    }
    {
        const __half* Kg = g_kh + ((size_t)h * T_DIM) * D_DIM;
        const __half* Vg = g_vh + ((size_t)h * T_DIM) * D_DIM;
        #pragma unroll
        for (int i = tid; i < 512; i += 256) {
            const int r = i >> 3, sg = i & 7;
            CP16(smem_u32(&Ks[0][r][sg * 8]), &Kg[r * D_DIM + sg * 8]);
            CP16(smem_u32(&Vs[0][r][sg * 8]), &Vg[r * D_DIM + sg * 8]);
        }
    }
    CP_COMMIT();
    {
        const __half* Kg = g_kh + ((size_t)h * T_DIM + 64) * D_DIM;
        const __half* Vg = g_vh + ((size_t)h * T_DIM + 64) * D_DIM;
        #pragma unroll
        for (int i = tid; i < 512; i += 256) {
            const int r = i >> 3, sg = i & 7;
            CP16(smem_u32(&Ks[1][r][sg * 8]), &Kg[r * D_DIM + sg * 8]);
            CP16(smem_u32(&Vs[1][r][sg * 8]), &Vg[r * D_DIM + sg * 8]);
        }
    }
    CP_COMMIT();

    uint32_t qf[4][4];
    float o[8][4];
    float lsum[4] = {0.0f, 0.0f, 0.0f, 0.0f};
    #pragma unroll
    for (int nt = 0; nt < 8; nt++)
        #pragma unroll
        for (int r = 0; r < 4; r++) o[nt][r] = 0.0f;
    float m0r = -1e30f, m1r = -1e30f;

    const int row0 = qb * 128 + w * 16 + g;
    const int row1 = row0 + 8;

    const uint32_t k_base = smem_u32(&Ks[0][(lane >> 4) * 8 + (lane & 7)][((lane >> 3) & 1) * 8]);
    const uint32_t v_base = smem_u32(&Vs[0][lane & 15][(lane >> 4) * 8]);

    for (int jb = 0; jb <= jend; jb++) {
        if (jb < jend) { CP_WAIT1(); } else { CP_WAIT0(); }
        __syncthreads();
        if (jb == 0) {
            const uint32_t qa = smem_u32(&Qs[w * 16 + (lane & 15)][(lane >> 4) * 8]);
            #pragma unroll
            for (int kt = 0; kt < 4; kt++)
                LDSM_X4(qf[kt][0], qf[kt][1], qf[kt][2], qf[kt][3], qa + kt * 32);
        }
        if (jb + 2 <= jend) {
            const int nb = (jb + 2) % 3;
            const __half* Kg = g_kh + ((size_t)h * T_DIM + (jb + 2) * 64) * D_DIM;
            const __half* Vg = g_vh + ((size_t)h * T_DIM + (jb + 2) * 64) * D_DIM;
            #pragma unroll
            for (int i = tid; i < 512; i += 256) {
                const int r = i >> 3, sg = i & 7;
                CP16(smem_u32(&Ks[nb][r][sg * 8]), &Kg[r * D_DIM + sg * 8]);
                CP16(smem_u32(&Vs[nb][r][sg * 8]), &Vg[r * D_DIM + sg * 8]);
            }
            CP_COMMIT();
        }
        const uint32_t boff = (uint32_t)(jb % 3) * KV_BUF_B;

        // ---- S = Q K^T (log2-domain scores) ----
        float s[8][4];
        #pragma unroll
        for (int nt = 0; nt < 8; nt++)
            #pragma unroll
            for (int r = 0; r < 4; r++) s[nt][r] = 0.0f;

        #pragma unroll
        for (int kt = 0; kt < 4; kt++) {
            #pragma unroll
            for (int p = 0; p < 4; p++) {
                uint32_t b0, b1, b2, b3;
                LDSM_X4(b0, b1, b2, b3, k_base + boff + p * 16 * 144 + kt * 32);
                MMA16816(s[2 * p], qf[kt], b0, b1);
                MMA16816(s[2 * p + 1], qf[kt], b2, b3);
            }
        }

        // ---- causal mask ----
        if (jb >= 2 * qb) {
            #pragma unroll
            for (int nt = 0; nt < 8; nt++) {
                const int cb = jb * 64 + nt * 8 + qd * 2;
                if (cb > row0)     s[nt][0] = -1e30f;
                if (cb + 1 > row0) s[nt][1] = -1e30f;
                if (cb > row1)     s[nt][2] = -1e30f;
                if (cb + 1 > row1) s[nt][3] = -1e30f;
            }
        }

        // ---- row max (f32, quad shuffles) ----
        float bm0 = s[0][0], bm1 = s[0][2];
        #pragma unroll
        for (int nt = 0; nt < 8; nt++) {
            bm0 = fmaxf(bm0, fmaxf(s[nt][0], s[nt][1]));
            bm1 = fmaxf(bm1, fmaxf(s[nt][2], s[nt][3]));
        }
        bm0 = fmaxf(bm0, __shfl_xor_sync(0xffffffffu, bm0, 1));
        bm0 = fmaxf(bm0, __shfl_xor_sync(0xffffffffu, bm0, 2));
        bm1 = fmaxf(bm1, __shfl_xor_sync(0xffffffffu, bm1, 1));
        bm1 = fmaxf(bm1, __shfl_xor_sync(0xffffffffu, bm1, 2));
        const float mn0 = fmaxf(m0r, bm0), mn1 = fmaxf(m1r, bm1);
        const float cr0 = ex2(m0r - mn0), cr1 = ex2(m1r - mn1);
        m0r = mn0; m1r = mn1;

        // rescale O and l accumulators
        #pragma unroll
        for (int nt = 0; nt < 8; nt++) {
            o[nt][0] *= cr0; o[nt][1] *= cr0;
            o[nt][2] *= cr1; o[nt][3] *= cr1;
        }
        lsum[0] *= cr0; lsum[1] *= cr0;
        lsum[2] *= cr1; lsum[3] *= cr1;

        // ---- P fragments: f32 subtract (exact), pack, MUFU ex2.f16x2 ----
        uint32_t pf[4][4];
        #pragma unroll
        for (int kt = 0; kt < 4; kt++) {
            pf[kt][0] = ex2h2(packh2(s[2 * kt][0] - mn0,     s[2 * kt][1] - mn0));
            pf[kt][1] = ex2h2(packh2(s[2 * kt][2] - mn1,     s[2 * kt][3] - mn1));
            pf[kt][2] = ex2h2(packh2(s[2 * kt + 1][0] - mn0, s[2 * kt + 1][1] - mn0));
            pf[kt][3] = ex2h2(packh2(s[2 * kt + 1][2] - mn1, s[2 * kt + 1][3] - mn1));
        }

        // ---- O += P V, and l += P ones ----
        #pragma unroll
        for (int kt = 0; kt < 4; kt++) {
            MMA16816(lsum, pf[kt], ONES_H2, ONES_H2);
            #pragma unroll
            for (int dt = 0; dt < 4; dt++) {
                uint32_t v0, v1, v2, v3;
                LDSM_X4T(v0, v1, v2, v3, v_base + boff + kt * 16 * 144 + dt * 32);
                MMA16816(o[2 * dt], pf[kt], v0, v1);
                MMA16816(o[2 * dt + 1], pf[kt], v2, v3);
            }
        }
    }

    // epilogue: normalize, write y fp16 [T][C]
    const float il0 = 1.0f / lsum[0], il1 = 1.0f / lsum[2];
    __half* y0 = g_yh + (size_t)row0 * C_DIM + h * D_DIM;
    __half* y1 = g_yh + (size_t)row1 * C_DIM + h * D_DIM;
    #pragma unroll
    for (int nt = 0; nt < 8; nt++) {
        const int d = nt * 8 + qd * 2;
        *(uint32_t*)&y0[d] = packh2(o[nt][0] * il0, o[nt][1] * il0);
        *(uint32_t*)&y1[d] = packh2(o[nt][2] * il1, o[nt][3] * il1);
    }
}

// ---------------------------------------------------------------------------
extern "C" void kernel_launch(void* const* d_in, const int* in_sizes, int n_in,
                              void* d_out, int out_size) {
    const float* x      = (const float*)d_in[0];
    // d_in[1] = causal mask, applied analytically
    const float* W_qkv  = (const float*)d_in[2];
    const float* b_qkv  = (const float*)d_in[3];
    const float* W_proj = (const float*)d_in[4];
    const float* b_proj = (const float*)d_in[5];
    float* out = (float*)d_out;

    static int init_done = 0;
    static __half *xh, *wq, *wp, *yh;
    if (!init_done) {
        cudaGetSymbolAddress((void**)&xh, g_xh);
        cudaGetSymbolAddress((void**)&wq, g_wq);
        cudaGetSymbolAddress((void**)&wp, g_wp);
        cudaGetSymbolAddress((void**)&yh, g_yh);
        cudaFuncSetAttribute(mma_gemm_kernel<0>,
                             cudaFuncAttributeMaxDynamicSharedMemorySize,
                             GEMM_SMEM_BYTES);
        cudaFuncSetAttribute(mma_gemm_kernel<1>,
                             cudaFuncAttributeMaxDynamicSharedMemorySize,
                             GEMM_SMEM_BYTES);
        cudaFuncSetAttribute(attn_kernel,
                             cudaFuncAttributeMaxDynamicSharedMemorySize,
                             ATTN_SMEM_BYTES);
        init_done = 1;
    }

    // prepasses: straight fp32->fp16 converts
    convert_f16_kernel<<<(T_DIM * C_DIM / 4 + 255) / 256, 256>>>(
        x, xh, T_DIM * C_DIM / 4);
    convert_f16_kernel<<<(C_DIM * C3_DIM / 4 + 255) / 256, 256>>>(
        W_qkv, wq, C_DIM * C3_DIM / 4);
    convert_f16_kernel<<<(C_DIM * C_DIM / 4 + 255) / 256, 256>>>(
        W_proj, wp, C_DIM * C_DIM / 4);

    // QKV GEMM -> fp16 Q(log2-scaled)/K/V
    mma_gemm_kernel<0><<<dim3(C3_DIM / 128, T_DIM / 128), 256, GEMM_SMEM_BYTES>>>(
        xh, wq, C3_DIM, b_qkv, nullptr);
    // Attention -> fp16 y
    attn_kernel<<<dim3(T_DIM / 128, H_DIM), 256, ATTN_SMEM_BYTES>>>();
    // Projection GEMM -> fp32 out
    mma_gemm_kernel<1><<<dim3(C_DIM / 128, T_DIM / 128), 256, GEMM_SMEM_BYTES>>>(
        yh, wp, C_DIM, b_proj, out);
}

// round 11
// speedup vs baseline: 1.0300x; 1.0300x over previous
#include <cuda_runtime.h>
#include <cuda_fp16.h>
#include <math.h>
#include <stdint.h>

#define T_DIM 4096
#define C_DIM 768
#define H_DIM 12
#define D_DIM 64
#define C3_DIM 2304

// ---------------------------------------------------------------------------
// Global scratch (allocation-free rule). 16B-aligned for uint4/cp.async.
// ---------------------------------------------------------------------------
__device__ __align__(16) __half g_qh[H_DIM * T_DIM * D_DIM];
__device__ __align__(16) __half g_kh[H_DIM * T_DIM * D_DIM];
__device__ __align__(16) __half g_vh[H_DIM * T_DIM * D_DIM];
__device__ __align__(16) __half g_xh[T_DIM * C_DIM];
__device__ __align__(16) __half g_yh[T_DIM * C_DIM];
__device__ __align__(16) __half g_wq[C_DIM * C3_DIM];    // W_qkv fp16 [K][N]
__device__ __align__(16) __half g_wp[C_DIM * C_DIM];     // W_proj fp16 [K][N]

// ---------------------------------------------------------------------------
// PTX helpers (sm_80-level: compile under plain sm_103 target)
// ---------------------------------------------------------------------------
__device__ __forceinline__ uint32_t smem_u32(const void* p) {
    uint32_t a;
    asm("{ .reg .u64 t; cvta.to.shared.u64 t, %1; cvt.u32.u64 %0, t; }"
        : "=r"(a) : "l"(p));
    return a;
}

#define CP16(dst, src) \
    asm volatile("cp.async.cg.shared.global [%0], [%1], 16;" \
                 :: "r"(dst), "l"(src))
#define CP_COMMIT() asm volatile("cp.async.commit_group;" ::: "memory")
#define CP_WAIT0()  asm volatile("cp.async.wait_group 0;" ::: "memory")

#define LDSM_X4(r0, r1, r2, r3, addr) \
    asm volatile("ldmatrix.sync.aligned.m8n8.x4.shared.b16 {%0,%1,%2,%3}, [%4];" \
                 : "=r"(r0), "=r"(r1), "=r"(r2), "=r"(r3) : "r"(addr))

#define LDSM_X4T(r0, r1, r2, r3, addr) \
    asm volatile("ldmatrix.sync.aligned.m8n8.x4.trans.shared.b16 {%0,%1,%2,%3}, [%4];" \
                 : "=r"(r0), "=r"(r1), "=r"(r2), "=r"(r3) : "r"(addr))

#define MMA16816(d, a, b0, b1) \
    asm volatile("mma.sync.aligned.m16n8k16.row.col.f32.f16.f16.f32 " \
                 "{%0,%1,%2,%3}, {%4,%5,%6,%7}, {%8,%9}, {%0,%1,%2,%3};" \
                 : "+f"((d)[0]), "+f"((d)[1]), "+f"((d)[2]), "+f"((d)[3]) \
                 : "r"((a)[0]), "r"((a)[1]), "r"((a)[2]), "r"((a)[3]), \
                   "r"(b0), "r"(b1))

__device__ __forceinline__ uint32_t packh2(float lo, float hi) {
    uint32_t d;
    asm("cvt.rn.f16x2.f32 %0, %1, %2;" : "=r"(d) : "f"(hi), "f"(lo));
    return d;
}
__device__ __forceinline__ uint32_t ex2h2(uint32_t a) {
    uint32_t d;
    asm("ex2.approx.f16x2 %0, %1;" : "=r"(d) : "r"(a));
    return d;
}
__device__ __forceinline__ float ex2(float x) {
    float y;
    asm("ex2.approx.ftz.f32 %0, %1;" : "=f"(y) : "f"(x));
    return y;
}

// ---------------------------------------------------------------------------
// Fused prepass: fp32 -> fp16 for x, W_qkv, W_proj in ONE launch.
// ---------------------------------------------------------------------------
#define N4_X  (T_DIM * C_DIM / 4)
#define N4_WQ (C_DIM * C3_DIM / 4)
#define N4_WP (C_DIM * C_DIM / 4)
#define N4_TOTAL (N4_X + N4_WQ + N4_WP)

__global__ void convert_all_kernel(const float* __restrict__ x,
                                   const float* __restrict__ wq,
                                   const float* __restrict__ wp,
                                   __half* __restrict__ xh,
                                   __half* __restrict__ wqh,
                                   __half* __restrict__ wph) {
    int i = blockIdx.x * blockDim.x + threadIdx.x;
    if (i >= N4_TOTAL) return;
    const float* src;
    __half* dst;
    int j = i;
    if (j < N4_X) { src = x; dst = xh; }
    else if ((j -= N4_X) < N4_WQ) { src = wq; dst = wqh; }
    else { j -= N4_WQ; src = wp; dst = wph; }
    float4 v = ((const float4*)src)[j];
    uint2 o;
    o.x = packh2(v.x, v.y);
    o.y = packh2(v.z, v.w);
    *(uint2*)&dst[4 * (size_t)j] = o;
}

// ---------------------------------------------------------------------------
// fp16 mma GEMM, 2-stage cp.async pipeline. C = A[M,K] @ B[K,N] (B row-major).
// Tile 128x128, BK=64, 8 warps (64x32 each).
// MODE 0: qkv scatter (Q pre-scaled by 0.125*log2e). MODE 1: fp32 out.
// ---------------------------------------------------------------------------
#define GA_BUF (128 * 72)               // halves per A stage
#define GB_BUF (64 * 136)               // halves per B stage
#define GA_BUF_B (GA_BUF * 2)
#define GB_BUF_B (GB_BUF * 2)
#define GEMM_SMEM_BYTES (2 * (GA_BUF + GB_BUF) * 2)

#define Q_SCALE 0.18033688011112042f    // 0.125 * log2(e)

template <int MODE>
__global__ __launch_bounds__(256, 2)
void mma_gemm_kernel(const __half* __restrict__ A,
                     const __half* __restrict__ B, int ldb,
                     const float* __restrict__ bias,
                     float* __restrict__ outp) {
    extern __shared__ __half sm[];
    __half (*As)[128][72] = (__half(*)[128][72])sm;
    __half (*Bs)[64][136] = (__half(*)[64][136])(sm + 2 * GA_BUF);

    const int tid = threadIdx.x;
    const int w = tid >> 5, lane = tid & 31;
    const int wm = w >> 2, wn = w & 3;
    const int g = lane >> 2, qd = lane & 3;
    const int m0 = blockIdx.y * 128;
    const int n0 = blockIdx.x * 128;

    float acc[4][4][4];
    #pragma unroll
    for (int mt = 0; mt < 4; mt++)
        #pragma unroll
        for (int nt = 0; nt < 4; nt++)
            #pragma unroll
            for (int r = 0; r < 4; r++) acc[mt][nt][r] = 0.0f;

    // prologue: stage chunk 0
    #pragma unroll
    for (int i = tid; i < 1024; i += 256) {
        const int ra = i >> 3, sga = i & 7;
        CP16(smem_u32(&As[0][ra][sga * 8]),
             &A[(size_t)(m0 + ra) * C_DIM + sga * 8]);
        const int rb = i >> 4, sgb = i & 15;
        CP16(smem_u32(&Bs[0][rb][sgb * 8]),
             &B[(size_t)rb * ldb + n0 + sgb * 8]);
    }
    CP_COMMIT();

    uint32_t a_base[4];
    #pragma unroll
    for (int mt = 0; mt < 4; mt++)
        a_base[mt] = smem_u32(&As[0][wm * 64 + mt * 16 + (lane & 15)][(lane >> 4) * 8]);
    const uint32_t b_base = smem_u32(&Bs[0][lane & 15][wn * 32 + (lane >> 4) * 8]);

    for (int c = 0; c < 12; c++) {
        CP_WAIT0();
        __syncthreads();
        if (c < 11) {
            const int k0 = (c + 1) * 64;
            const int nb = (c + 1) & 1;
            #pragma unroll
            for (int i = tid; i < 1024; i += 256) {
                const int ra = i >> 3, sga = i & 7;
                CP16(smem_u32(&As[nb][ra][sga * 8]),
                     &A[(size_t)(m0 + ra) * C_DIM + k0 + sga * 8]);
                const int rb = i >> 4, sgb = i & 15;
                CP16(smem_u32(&Bs[nb][rb][sgb * 8]),
                     &B[(size_t)(k0 + rb) * ldb + n0 + sgb * 8]);
            }
            CP_COMMIT();
        }
        const uint32_t boffA = (uint32_t)(c & 1) * GA_BUF_B;
        const uint32_t boffB = (uint32_t)(c & 1) * GB_BUF_B;
        #pragma unroll
        for (int kt = 0; kt < 4; kt++) {
            uint32_t af[4][4];
            #pragma unroll
            for (int mt = 0; mt < 4; mt++)
                LDSM_X4(af[mt][0], af[mt][1], af[mt][2], af[mt][3],
                        a_base[mt] + boffA + kt * 32);
            #pragma unroll
            for (int p = 0; p < 2; p++) {
                uint32_t b0, b1, b2, b3;
                LDSM_X4T(b0, b1, b2, b3,
                         b_base + boffB + kt * (16 * 272) + p * 32);
                #pragma unroll
                for (int mt = 0; mt < 4; mt++) {
                    MMA16816(acc[mt][2 * p], af[mt], b0, b1);
                    MMA16816(acc[mt][2 * p + 1], af[mt], b2, b3);
                }
            }
        }
    }

    // epilogue
    #pragma unroll
    for (int nt = 0; nt < 4; nt++) {
        const int f = n0 + wn * 32 + nt * 8 + qd * 2;
        const float b0v = bias[f], b1v = bias[f + 1];
        if (MODE == 0) {
            const int sec = f / C_DIM;
            const int cc = f - sec * C_DIM;
            const int hh = cc >> 6, d = cc & 63;
            const float sc = (sec == 0) ? Q_SCALE : 1.0f;
            __half* dst = (sec == 0) ? g_qh : (sec == 1) ? g_kh : g_vh;
            #pragma unroll
            for (int mt = 0; mt < 4; mt++) {
                const int m = m0 + wm * 64 + mt * 16 + g;
                *(uint32_t*)&dst[((size_t)hh * T_DIM + m) * D_DIM + d] =
                    packh2((acc[mt][nt][0] + b0v) * sc, (acc[mt][nt][1] + b1v) * sc);
                *(uint32_t*)&dst[((size_t)hh * T_DIM + m + 8) * D_DIM + d] =
                    packh2((acc[mt][nt][2] + b0v) * sc, (acc[mt][nt][3] + b1v) * sc);
            }
        } else {
            #pragma unroll
            for (int mt = 0; mt < 4; mt++) {
                const int m = m0 + wm * 64 + mt * 16 + g;
                float2 r0 = make_float2(acc[mt][nt][0] + b0v, acc[mt][nt][1] + b1v);
                float2 r1 = make_float2(acc[mt][nt][2] + b0v, acc[mt][nt][3] + b1v);
                *(float2*)&outp[(size_t)m * C_DIM + f] = r0;
                *(float2*)&outp[(size_t)(m + 8) * C_DIM + f] = r1;
            }
        }
    }
}

// ---------------------------------------------------------------------------
// Causal flash attention, fp16 mma, 2-stage cp.async K/V pipeline.
// CTA: 128 q-rows, 8 warps (16 rows each), key blocks of 64.
// Softmax log2-domain; f32 subtract, f16x2 ex2 -> P fragments; row-sum l via
// ones-column MMA; O/l rescale skipped when the running max didn't change.
// ---------------------------------------------------------------------------
#define KV_BUF (64 * 72)
#define KV_BUF_B (KV_BUF * 2)
#define ATTN_SMEM_BYTES ((128 * 72 + 4 * KV_BUF) * 2)
#define ONES_H2 0x3C003C00u             // (1.0h, 1.0h)

__global__ __launch_bounds__(256, 2)
void attn_kernel() {
    extern __shared__ __half sm[];
    __half (*Qs)[72] = (__half(*)[72])sm;
    __half (*Ks)[64][72] = (__half(*)[64][72])(sm + 128 * 72);
    __half (*Vs)[64][72] = (__half(*)[64][72])(sm + 128 * 72 + 2 * KV_BUF);

    const int h = blockIdx.y;
    const int qb = gridDim.x - 1 - blockIdx.x;   // heavy blocks first
    const int tid = threadIdx.x;
    const int w = tid >> 5, lane = tid & 31;
    const int g = lane >> 2, qd = lane & 3;

    // stage Q + K/V block 0 as one async group
    const __half* Qg = g_qh + ((size_t)h * T_DIM + qb * 128) * D_DIM;
    #pragma unroll
    for (int i = tid; i < 1024; i += 256) {
        const int r = i >> 3, sg = i & 7;
        CP16(smem_u32(&Qs[r][sg * 8]), &Qg[r * D_DIM + sg * 8]);
    }
    {
        const __half* Kg = g_kh + ((size_t)h * T_DIM) * D_DIM;
        const __half* Vg = g_vh + ((size_t)h * T_DIM) * D_DIM;
        #pragma unroll
        for (int i = tid; i < 512; i += 256) {
            const int r = i >> 3, sg = i & 7;
            CP16(smem_u32(&Ks[0][r][sg * 8]), &Kg[r * D_DIM + sg * 8]);
            CP16(smem_u32(&Vs[0][r][sg * 8]), &Vg[r * D_DIM + sg * 8]);
        }
    }
    CP_COMMIT();

    uint32_t qf[4][4];
    float o[8][4];
    float lsum[4] = {0.0f, 0.0f, 0.0f, 0.0f};
    #pragma unroll
    for (int nt = 0; nt < 8; nt++)
        #pragma unroll
        for (int r = 0; r < 4; r++) o[nt][r] = 0.0f;
    float m0r = -1e30f, m1r = -1e30f;

    const int row0 = qb * 128 + w * 16 + g;
    const int row1 = row0 + 8;

    const uint32_t k_base = smem_u32(&Ks[0][(lane >> 4) * 8 + (lane & 7)][((lane >> 3) & 1) * 8]);
    const uint32_t v_base = smem_u32(&Vs[0][lane & 15][(lane >> 4) * 8]);

    const int jend = 2 * qb + 1;
    for (int jb = 0; jb <= jend; jb++) {
        CP_WAIT0();
        __syncthreads();
        if (jb == 0) {
            const uint32_t qa = smem_u32(&Qs[w * 16 + (lane & 15)][(lane >> 4) * 8]);
            #pragma unroll
            for (int kt = 0; kt < 4; kt++)
                LDSM_X4(qf[kt][0], qf[kt][1], qf[kt][2], qf[kt][3], qa + kt * 32);
        }
        if (jb < jend) {
            const int nb = (jb + 1) & 1;
            const __half* Kg = g_kh + ((size_t)h * T_DIM + (jb + 1) * 64) * D_DIM;
            const __half* Vg = g_vh + ((size_t)h * T_DIM + (jb + 1) * 64) * D_DIM;
            #pragma unroll
            for (int i = tid; i < 512; i += 256) {
                const int r = i >> 3, sg = i & 7;
                CP16(smem_u32(&Ks[nb][r][sg * 8]), &Kg[r * D_DIM + sg * 8]);
                CP16(smem_u32(&Vs[nb][r][sg * 8]), &Vg[r * D_DIM + sg * 8]);
            }
            CP_COMMIT();
        }
        const uint32_t boff = (uint32_t)(jb & 1) * KV_BUF_B;

        // ---- S = Q K^T (log2-domain scores) ----
        float s[8][4];
        #pragma unroll
        for (int nt = 0; nt < 8; nt++)
            #pragma unroll
            for (int r = 0; r < 4; r++) s[nt][r] = 0.0f;

        #pragma unroll
        for (int kt = 0; kt < 4; kt++) {
            #pragma unroll
            for (int p = 0; p < 4; p++) {
                uint32_t b0, b1, b2, b3;
                LDSM_X4(b0, b1, b2, b3, k_base + boff + p * 16 * 144 + kt * 32);
                MMA16816(s[2 * p], qf[kt], b0, b1);
                MMA16816(s[2 * p + 1], qf[kt], b2, b3);
            }
        }

        // ---- causal mask ----
        if (jb >= 2 * qb) {
            #pragma unroll
            for (int nt = 0; nt < 8; nt++) {
                const int cb = jb * 64 + nt * 8 + qd * 2;
                if (cb > row0)     s[nt][0] = -1e30f;
                if (cb + 1 > row0) s[nt][1] = -1e30f;
                if (cb > row1)     s[nt][2] = -1e30f;
                if (cb + 1 > row1) s[nt][3] = -1e30f;
            }
        }

        // ---- row max (f32, quad shuffles) ----
        float bm0 = s[0][0], bm1 = s[0][2];
        #pragma unroll
        for (int nt = 0; nt < 8; nt++) {
            bm0 = fmaxf(bm0, fmaxf(s[nt][0], s[nt][1]));
            bm1 = fmaxf(bm1, fmaxf(s[nt][2], s[nt][3]));
        }
        bm0 = fmaxf(bm0, __shfl_xor_sync(0xffffffffu, bm0, 1));
        bm0 = fmaxf(bm0, __shfl_xor_sync(0xffffffffu, bm0, 2));
        bm1 = fmaxf(bm1, __shfl_xor_sync(0xffffffffu, bm1, 1));
        bm1 = fmaxf(bm1, __shfl_xor_sync(0xffffffffu, bm1, 2));

        // ---- rescale only when the running max actually moved ----
        if (__any_sync(0xffffffffu, (bm0 > m0r) | (bm1 > m1r))) {
            const float mn0 = fmaxf(m0r, bm0), mn1 = fmaxf(m1r, bm1);
            const float cr0 = ex2(m0r - mn0), cr1 = ex2(m1r - mn1);
            m0r = mn0; m1r = mn1;
            #pragma unroll
            for (int nt = 0; nt < 8; nt++) {
                o[nt][0] *= cr0; o[nt][1] *= cr0;
                o[nt][2] *= cr1; o[nt][3] *= cr1;
            }
            lsum[0] *= cr0; lsum[1] *= cr0;
            lsum[2] *= cr1; lsum[3] *= cr1;
        }

        // ---- P fragments: f32 subtract (exact), pack, MUFU ex2.f16x2 ----
        const float mn0 = m0r, mn1 = m1r;
        uint32_t pf[4][4];
        #pragma unroll
        for (int kt = 0; kt < 4; kt++) {
            pf[kt][0] = ex2h2(packh2(s[2 * kt][0] - mn0,     s[2 * kt][1] - mn0));
            pf[kt][1] = ex2h2(packh2(s[2 * kt][2] - mn1,     s[2 * kt][3] - mn1));
            pf[kt][2] = ex2h2(packh2(s[2 * kt + 1][0] - mn0, s[2 * kt + 1][1] - mn0));
            pf[kt][3] = ex2h2(packh2(s[2 * kt + 1][2] - mn1, s[2 * kt + 1][3] - mn1));
        }

        // ---- O += P V, and l += P ones ----
        #pragma unroll
        for (int kt = 0; kt < 4; kt++) {
            MMA16816(lsum, pf[kt], ONES_H2, ONES_H2);
            #pragma unroll
            for (int dt = 0; dt < 4; dt++) {
                uint32_t v0, v1, v2, v3;
                LDSM_X4T(v0, v1, v2, v3, v_base + boff + kt * 16 * 144 + dt * 32);
                MMA16816(o[2 * dt], pf[kt], v0, v1);
                MMA16816(o[2 * dt + 1], pf[kt], v2, v3);
            }
        }
    }

    // epilogue: normalize, write y fp16 [T][C]
    const float il0 = 1.0f / lsum[0], il1 = 1.0f / lsum[2];
    __half* y0 = g_yh + (size_t)row0 * C_DIM + h * D_DIM;
    __half* y1 = g_yh + (size_t)row1 * C_DIM + h * D_DIM;
    #pragma unroll
    for (int nt = 0; nt < 8; nt++) {
        const int d = nt * 8 + qd * 2;
        *(uint32_t*)&y0[d] = packh2(o[nt][0] * il0, o[nt][1] * il0);
        *(uint32_t*)&y1[d] = packh2(o[nt][2] * il1, o[nt][3] * il1);
    }
}

// ---------------------------------------------------------------------------
extern "C" void kernel_launch(void* const* d_in, const int* in_sizes, int n_in,
                              void* d_out, int out_size) {
    const float* x      = (const float*)d_in[0];
    // d_in[1] = causal mask, applied analytically
    const float* W_qkv  = (const float*)d_in[2];
    const float* b_qkv  = (const float*)d_in[3];
    const float* W_proj = (const float*)d_in[4];
    const float* b_proj = (const float*)d_in[5];
    float* out = (float*)d_out;

    static int init_done = 0;
    static __half *xh, *wq, *wp, *yh;
    if (!init_done) {
        cudaGetSymbolAddress((void**)&xh, g_xh);
        cudaGetSymbolAddress((void**)&wq, g_wq);
        cudaGetSymbolAddress((void**)&wp, g_wp);
        cudaGetSymbolAddress((void**)&yh, g_yh);
        cudaFuncSetAttribute(mma_gemm_kernel<0>,
                             cudaFuncAttributeMaxDynamicSharedMemorySize,
                             GEMM_SMEM_BYTES);
        cudaFuncSetAttribute(mma_gemm_kernel<1>,
                             cudaFuncAttributeMaxDynamicSharedMemorySize,
                             GEMM_SMEM_BYTES);
        cudaFuncSetAttribute(attn_kernel,
                             cudaFuncAttributeMaxDynamicSharedMemorySize,
                             ATTN_SMEM_BYTES);
        init_done = 1;
    }

    // fused prepass: all fp32 -> fp16 converts in one launch
    convert_all_kernel<<<(N4_TOTAL + 255) / 256, 256>>>(
        x, W_qkv, W_proj, xh, wq, wp);

    // QKV GEMM -> fp16 Q(log2-scaled)/K/V
    mma_gemm_kernel<0><<<dim3(C3_DIM / 128, T_DIM / 128), 256, GEMM_SMEM_BYTES>>>(
        xh, wq, C3_DIM, b_qkv, nullptr);
    // Attention -> fp16 y
    attn_kernel<<<dim3(T_DIM / 128, H_DIM), 256, ATTN_SMEM_BYTES>>>();
    // Projection GEMM -> fp32 out
    mma_gemm_kernel<1><<<dim3(C_DIM / 128, T_DIM / 128), 256, GEMM_SMEM_BYTES>>>(
        yh, wp, C_DIM, b_proj, out);
}

// round 13
// speedup vs baseline: 1.0528x; 1.0222x over previous
#include <cuda_runtime.h>
#include <cuda_fp16.h>
#include <math.h>
#include <stdint.h>

#define T_DIM 4096
#define C_DIM 768
#define H_DIM 12
#define D_DIM 64
#define C3_DIM 2304

// ---------------------------------------------------------------------------
// Global scratch (allocation-free rule). 16B-aligned for uint4/cp.async.
// ---------------------------------------------------------------------------
__device__ __align__(16) __half g_qh[H_DIM * T_DIM * D_DIM];
__device__ __align__(16) __half g_kh[H_DIM * T_DIM * D_DIM];
__device__ __align__(16) __half g_vh[H_DIM * T_DIM * D_DIM];
__device__ __align__(16) __half g_xh[T_DIM * C_DIM];
__device__ __align__(16) __half g_yh[T_DIM * C_DIM];
__device__ __align__(16) __half g_wq[C_DIM * C3_DIM];    // W_qkv fp16 [K][N]
__device__ __align__(16) __half g_wp[C_DIM * C_DIM];     // W_proj fp16 [K][N]

// ---------------------------------------------------------------------------
// PTX helpers (sm_80-level: compile under plain sm_103 target)
// ---------------------------------------------------------------------------
__device__ __forceinline__ uint32_t smem_u32(const void* p) {
    uint32_t a;
    asm("{ .reg .u64 t; cvta.to.shared.u64 t, %1; cvt.u32.u64 %0, t; }"
        : "=r"(a) : "l"(p));
    return a;
}

#define CP16(dst, src) \
    asm volatile("cp.async.cg.shared.global [%0], [%1], 16;" \
                 :: "r"(dst), "l"(src))
#define CP_COMMIT() asm volatile("cp.async.commit_group;" ::: "memory")
#define CP_WAIT0()  asm volatile("cp.async.wait_group 0;" ::: "memory")

#define LDSM_X4(r0, r1, r2, r3, addr) \
    asm volatile("ldmatrix.sync.aligned.m8n8.x4.shared.b16 {%0,%1,%2,%3}, [%4];" \
                 : "=r"(r0), "=r"(r1), "=r"(r2), "=r"(r3) : "r"(addr))

#define LDSM_X4T(r0, r1, r2, r3, addr) \
    asm volatile("ldmatrix.sync.aligned.m8n8.x4.trans.shared.b16 {%0,%1,%2,%3}, [%4];" \
                 : "=r"(r0), "=r"(r1), "=r"(r2), "=r"(r3) : "r"(addr))

#define MMA16816(d, a, b0, b1) \
    asm volatile("mma.sync.aligned.m16n8k16.row.col.f32.f16.f16.f32 " \
                 "{%0,%1,%2,%3}, {%4,%5,%6,%7}, {%8,%9}, {%0,%1,%2,%3};" \
                 : "+f"((d)[0]), "+f"((d)[1]), "+f"((d)[2]), "+f"((d)[3]) \
                 : "r"((a)[0]), "r"((a)[1]), "r"((a)[2]), "r"((a)[3]), \
                   "r"(b0), "r"(b1))

__device__ __forceinline__ uint32_t packh2(float lo, float hi) {
    uint32_t d;
    asm("cvt.rn.f16x2.f32 %0, %1, %2;" : "=r"(d) : "f"(hi), "f"(lo));
    return d;
}
__device__ __forceinline__ uint32_t ex2h2(uint32_t a) {
    uint32_t d;
    asm("ex2.approx.f16x2 %0, %1;" : "=r"(d) : "r"(a));
    return d;
}
__device__ __forceinline__ float ex2(float x) {
    float y;
    asm("ex2.approx.ftz.f32 %0, %1;" : "=f"(y) : "f"(x));
    return y;
}

// ---------------------------------------------------------------------------
// Fused prepass: fp32 -> fp16 for x, W_qkv, W_proj in ONE launch.
// ---------------------------------------------------------------------------
#define N4_X  (T_DIM * C_DIM / 4)
#define N4_WQ (C_DIM * C3_DIM / 4)
#define N4_WP (C_DIM * C_DIM / 4)
#define N4_TOTAL (N4_X + N4_WQ + N4_WP)

__global__ void convert_all_kernel(const float* __restrict__ x,
                                   const float* __restrict__ wq,
                                   const float* __restrict__ wp,
                                   __half* __restrict__ xh,
                                   __half* __restrict__ wqh,
                                   __half* __restrict__ wph) {
    int i = blockIdx.x * blockDim.x + threadIdx.x;
    if (i >= N4_TOTAL) return;
    const float* src;
    __half* dst;
    int j = i;
    if (j < N4_X) { src = x; dst = xh; }
    else if ((j -= N4_X) < N4_WQ) { src = wq; dst = wqh; }
    else { j -= N4_WQ; src = wp; dst = wph; }
    float4 v = ((const float4*)src)[j];
    uint2 o;
    o.x = packh2(v.x, v.y);
    o.y = packh2(v.z, v.w);
    *(uint2*)&dst[4 * (size_t)j] = o;
}

// ---------------------------------------------------------------------------
// fp16 mma GEMM, 2-stage cp.async pipeline. C = A[M,K] @ B[K,N] (B row-major).
// Tile 64x128, BK=64, 128 threads / 4 warps (warp tile 64x32), 4 CTAs/SM.
// MODE 0: qkv scatter (Q pre-scaled by 0.125*log2e). MODE 1: fp32 out.
// ---------------------------------------------------------------------------
#define GA_BUF (64 * 72)                // halves per A stage
#define GB_BUF (64 * 136)               // halves per B stage
#define GA_BUF_B (GA_BUF * 2)
#define GB_BUF_B (GB_BUF * 2)
#define GEMM_SMEM_BYTES (2 * (GA_BUF + GB_BUF) * 2)

#define Q_SCALE 0.18033688011112042f    // 0.125 * log2(e)

template <int MODE>
__global__ __launch_bounds__(128, 4)
void mma_gemm_kernel(const __half* __restrict__ A,
                     const __half* __restrict__ B, int ldb,
                     const float* __restrict__ bias,
                     float* __restrict__ outp) {
    extern __shared__ __half sm[];
    __half (*As)[64][72] = (__half(*)[64][72])sm;
    __half (*Bs)[64][136] = (__half(*)[64][136])(sm + 2 * GA_BUF);

    const int tid = threadIdx.x;
    const int wn = tid >> 5, lane = tid & 31;
    const int g = lane >> 2, qd = lane & 3;
    const int m0 = blockIdx.y * 64;
    const int n0 = blockIdx.x * 128;

    float acc[4][4][4];
    #pragma unroll
    for (int mt = 0; mt < 4; mt++)
        #pragma unroll
        for (int nt = 0; nt < 4; nt++)
            #pragma unroll
            for (int r = 0; r < 4; r++) acc[mt][nt][r] = 0.0f;

    // prologue: stage chunk 0
    #pragma unroll
    for (int i = tid; i < 512; i += 128) {
        const int ra = i >> 3, sga = i & 7;
        CP16(smem_u32(&As[0][ra][sga * 8]),
             &A[(size_t)(m0 + ra) * C_DIM + sga * 8]);
    }
    #pragma unroll
    for (int i = tid; i < 1024; i += 128) {
        const int rb = i >> 4, sgb = i & 15;
        CP16(smem_u32(&Bs[0][rb][sgb * 8]),
             &B[(size_t)rb * ldb + n0 + sgb * 8]);
    }
    CP_COMMIT();

    uint32_t a_base[4];
    #pragma unroll
    for (int mt = 0; mt < 4; mt++)
        a_base[mt] = smem_u32(&As[0][mt * 16 + (lane & 15)][(lane >> 4) * 8]);
    const uint32_t b_base = smem_u32(&Bs[0][lane & 15][wn * 32 + (lane >> 4) * 8]);

    for (int c = 0; c < 12; c++) {
        CP_WAIT0();
        __syncthreads();
        if (c < 11) {
            const int k0 = (c + 1) * 64;
            const int nb = (c + 1) & 1;
            #pragma unroll
            for (int i = tid; i < 512; i += 128) {
                const int ra = i >> 3, sga = i & 7;
                CP16(smem_u32(&As[nb][ra][sga * 8]),
                     &A[(size_t)(m0 + ra) * C_DIM + k0 + sga * 8]);
            }
            #pragma unroll
            for (int i = tid; i < 1024; i += 128) {
                const int rb = i >> 4, sgb = i & 15;
                CP16(smem_u32(&Bs[nb][rb][sgb * 8]),
                     &B[(size_t)(k0 + rb) * ldb + n0 + sgb * 8]);
            }
            CP_COMMIT();
        }
        const uint32_t boffA = (uint32_t)(c & 1) * GA_BUF_B;
        const uint32_t boffB = (uint32_t)(c & 1) * GB_BUF_B;
        #pragma unroll
        for (int kt = 0; kt < 4; kt++) {
            uint32_t af[4][4];
            #pragma unroll
            for (int mt = 0; mt < 4; mt++)
                LDSM_X4(af[mt][0], af[mt][1], af[mt][2], af[mt][3],
                        a_base[mt] + boffA + kt * 32);
            #pragma unroll
            for (int p = 0; p < 2; p++) {
                uint32_t b0, b1, b2, b3;
                LDSM_X4T(b0, b1, b2, b3,
                         b_base + boffB + kt * (16 * 272) + p * 32);
                #pragma unroll
                for (int mt = 0; mt < 4; mt++) {
                    MMA16816(acc[mt][2 * p], af[mt], b0, b1);
                    MMA16816(acc[mt][2 * p + 1], af[mt], b2, b3);
                }
            }
        }
    }

    // epilogue
    #pragma unroll
    for (int nt = 0; nt < 4; nt++) {
        const int f = n0 + wn * 32 + nt * 8 + qd * 2;
        const float b0v = bias[f], b1v = bias[f + 1];
        if (MODE == 0) {
            const int sec = f / C_DIM;
            const int cc = f - sec * C_DIM;
            const int hh = cc >> 6, d = cc & 63;
            const float sc = (sec == 0) ? Q_SCALE : 1.0f;
            __half* dst = (sec == 0) ? g_qh : (sec == 1) ? g_kh : g_vh;
            #pragma unroll
            for (int mt = 0; mt < 4; mt++) {
                const int m = m0 + mt * 16 + g;
                *(uint32_t*)&dst[((size_t)hh * T_DIM + m) * D_DIM + d] =
                    packh2((acc[mt][nt][0] + b0v) * sc, (acc[mt][nt][1] + b1v) * sc);
                *(uint32_t*)&dst[((size_t)hh * T_DIM + m + 8) * D_DIM + d] =
                    packh2((acc[mt][nt][2] + b0v) * sc, (acc[mt][nt][3] + b1v) * sc);
            }
        } else {
            #pragma unroll
            for (int mt = 0; mt < 4; mt++) {
                const int m = m0 + mt * 16 + g;
                float2 r0 = make_float2(acc[mt][nt][0] + b0v, acc[mt][nt][1] + b1v);
                float2 r1 = make_float2(acc[mt][nt][2] + b0v, acc[mt][nt][3] + b1v);
                *(float2*)&outp[(size_t)m * C_DIM + f] = r0;
                *(float2*)&outp[(size_t)(m + 8) * C_DIM + f] = r1;
            }
        }
    }
}

// ---------------------------------------------------------------------------
// Causal flash attention, fp16 mma, 2-stage cp.async K/V pipeline.
// CTA: 128 q-rows, 8 warps (16 rows each), key blocks of 64.
// Softmax log2-domain; f32 subtract, f16x2 ex2 -> P fragments; row-sum l via
// ones-column MMA; warps skip fully-masked diagonal blocks entirely.
// ---------------------------------------------------------------------------
#define KV_BUF (64 * 72)
#define KV_BUF_B (KV_BUF * 2)
#define ATTN_SMEM_BYTES ((128 * 72 + 4 * KV_BUF) * 2)
#define ONES_H2 0x3C003C00u             // (1.0h, 1.0h)

__global__ __launch_bounds__(256, 2)
void attn_kernel() {
    extern __shared__ __half sm[];
    __half (*Qs)[72] = (__half(*)[72])sm;
    __half (*Ks)[64][72] = (__half(*)[64][72])(sm + 128 * 72);
    __half (*Vs)[64][72] = (__half(*)[64][72])(sm + 128 * 72 + 2 * KV_BUF);

    const int h = blockIdx.y;
    const int qb = gridDim.x - 1 - blockIdx.x;   // heavy blocks first
    const int tid = threadIdx.x;
    const int w = tid >> 5, lane = tid & 31;
    const int g = lane >> 2, qd = lane & 3;

    // stage Q + K/V block 0 as one async group
    const __half* Qg = g_qh + ((size_t)h * T_DIM + qb * 128) * D_DIM;
    #pragma unroll
    for (int i = tid; i < 1024; i += 256) {
        const int r = i >> 3, sg = i & 7;
        CP16(smem_u32(&Qs[r][sg * 8]), &Qg[r * D_DIM + sg * 8]);
    }
    {
        const __half* Kg = g_kh + ((size_t)h * T_DIM) * D_DIM;
        const __half* Vg = g_vh + ((size_t)h * T_DIM) * D_DIM;
        #pragma unroll
        for (int i = tid; i < 512; i += 256) {
            const int r = i >> 3, sg = i & 7;
            CP16(smem_u32(&Ks[0][r][sg * 8]), &Kg[r * D_DIM + sg * 8]);
            CP16(smem_u32(&Vs[0][r][sg * 8]), &Vg[r * D_DIM + sg * 8]);
        }
    }
    CP_COMMIT();

    uint32_t qf[4][4];
    float o[8][4];
    float lsum[4] = {0.0f, 0.0f, 0.0f, 0.0f};
    #pragma unroll
    for (int nt = 0; nt < 8; nt++)
        #pragma unroll
        for (int r = 0; r < 4; r++) o[nt][r] = 0.0f;
    float m0r = -1e30f, m1r = -1e30f;

    const int row0 = qb * 128 + w * 16 + g;
    const int row1 = row0 + 8;
    const int rmax_w = qb * 128 + w * 16 + 15;   // warp's max q row

    const uint32_t k_base = smem_u32(&Ks[0][(lane >> 4) * 8 + (lane & 7)][((lane >> 3) & 1) * 8]);
    const uint32_t v_base = smem_u32(&Vs[0][lane & 15][(lane >> 4) * 8]);

    const int jend = 2 * qb + 1;
    for (int jb = 0; jb <= jend; jb++) {
        CP_WAIT0();
        __syncthreads();
        if (jb == 0) {
            const uint32_t qa = smem_u32(&Qs[w * 16 + (lane & 15)][(lane >> 4) * 8]);
            #pragma unroll
            for (int kt = 0; kt < 4; kt++)
                LDSM_X4(qf[kt][0], qf[kt][1], qf[kt][2], qf[kt][3], qa + kt * 32);
        }
        if (jb < jend) {
            const int nb = (jb + 1) & 1;
            const __half* Kg = g_kh + ((size_t)h * T_DIM + (jb + 1) * 64) * D_DIM;
            const __half* Vg = g_vh + ((size_t)h * T_DIM + (jb + 1) * 64) * D_DIM;
            #pragma unroll
            for (int i = tid; i < 512; i += 256) {
                const int r = i >> 3, sg = i & 7;
                CP16(smem_u32(&Ks[nb][r][sg * 8]), &Kg[r * D_DIM + sg * 8]);
                CP16(smem_u32(&Vs[nb][r][sg * 8]), &Vg[r * D_DIM + sg * 8]);
            }
            CP_COMMIT();
        }
        // fully-masked block for this warp: P == 0, nothing to do
        if (jb * 64 > rmax_w) continue;

        const uint32_t boff = (uint32_t)(jb & 1) * KV_BUF_B;

        // ---- S = Q K^T (log2-domain scores) ----
        float s[8][4];
        #pragma unroll
        for (int nt = 0; nt < 8; nt++)
            #pragma unroll
            for (int r = 0; r < 4; r++) s[nt][r] = 0.0f;

        #pragma unroll
        for (int kt = 0; kt < 4; kt++) {
            #pragma unroll
            for (int p = 0; p < 4; p++) {
                uint32_t b0, b1, b2, b3;
                LDSM_X4(b0, b1, b2, b3, k_base + boff + p * 16 * 144 + kt * 32);
                MMA16816(s[2 * p], qf[kt], b0, b1);
                MMA16816(s[2 * p + 1], qf[kt], b2, b3);
            }
        }

        // ---- causal mask ----
        if (jb >= 2 * qb) {
            #pragma unroll
            for (int nt = 0; nt < 8; nt++) {
                const int cb = jb * 64 + nt * 8 + qd * 2;
                if (cb > row0)     s[nt][0] = -1e30f;
                if (cb + 1 > row0) s[nt][1] = -1e30f;
                if (cb > row1)     s[nt][2] = -1e30f;
                if (cb + 1 > row1) s[nt][3] = -1e30f;
            }
        }

        // ---- row max (f32, quad shuffles) ----
        float bm0 = s[0][0], bm1 = s[0][2];
        #pragma unroll
        for (int nt = 0; nt < 8; nt++) {
            bm0 = fmaxf(bm0, fmaxf(s[nt][0], s[nt][1]));
            bm1 = fmaxf(bm1, fmaxf(s[nt][2], s[nt][3]));
        }
        bm0 = fmaxf(bm0, __shfl_xor_sync(0xffffffffu, bm0, 1));
        bm0 = fmaxf(bm0, __shfl_xor_sync(0xffffffffu, bm0, 2));
        bm1 = fmaxf(bm1, __shfl_xor_sync(0xffffffffu, bm1, 1));
        bm1 = fmaxf(bm1, __shfl_xor_sync(0xffffffffu, bm1, 2));

        // ---- rescale only when the running max actually moved ----
        if (__any_sync(0xffffffffu, (bm0 > m0r) | (bm1 > m1r))) {
            const float mn0 = fmaxf(m0r, bm0), mn1 = fmaxf(m1r, bm1);
            const float cr0 = ex2(m0r - mn0), cr1 = ex2(m1r - mn1);
            m0r = mn0; m1r = mn1;
            #pragma unroll
            for (int nt = 0; nt < 8; nt++) {
                o[nt][0] *= cr0; o[nt][1] *= cr0;
                o[nt][2] *= cr1; o[nt][3] *= cr1;
            }
            lsum[0] *= cr0; lsum[1] *= cr0;
            lsum[2] *= cr1; lsum[3] *= cr1;
        }

        // ---- P fragments: f32 subtract (exact), pack, MUFU ex2.f16x2 ----
        const float mn0 = m0r, mn1 = m1r;
        uint32_t pf[4][4];
        #pragma unroll
        for (int kt = 0; kt < 4; kt++) {
            pf[kt][0] = ex2h2(packh2(s[2 * kt][0] - mn0,     s[2 * kt][1] - mn0));
            pf[kt][1] = ex2h2(packh2(s[2 * kt][2] - mn1,     s[2 * kt][3] - mn1));
            pf[kt][2] = ex2h2(packh2(s[2 * kt + 1][0] - mn0, s[2 * kt + 1][1] - mn0));
            pf[kt][3] = ex2h2(packh2(s[2 * kt + 1][2] - mn1, s[2 * kt + 1][3] - mn1));
        }

        // ---- O += P V, and l += P ones ----
        #pragma unroll
        for (int kt = 0; kt < 4; kt++) {
            MMA16816(lsum, pf[kt], ONES_H2, ONES_H2);
            #pragma unroll
            for (int dt = 0; dt < 4; dt++) {
                uint32_t v0, v1, v2, v3;
                LDSM_X4T(v0, v1, v2, v3, v_base + boff + kt * 16 * 144 + dt * 32);
                MMA16816(o[2 * dt], pf[kt], v0, v1);
                MMA16816(o[2 * dt + 1], pf[kt], v2, v3);
            }
        }
    }

    // epilogue: normalize, write y fp16 [T][C]
    const float il0 = 1.0f / lsum[0], il1 = 1.0f / lsum[2];
    __half* y0 = g_yh + (size_t)row0 * C_DIM + h * D_DIM;
    __half* y1 = g_yh + (size_t)row1 * C_DIM + h * D_DIM;
    #pragma unroll
    for (int nt = 0; nt < 8; nt++) {
        const int d = nt * 8 + qd * 2;
        *(uint32_t*)&y0[d] = packh2(o[nt][0] * il0, o[nt][1] * il0);
        *(uint32_t*)&y1[d] = packh2(o[nt][2] * il1, o[nt][3] * il1);
    }
}

// ---------------------------------------------------------------------------
extern "C" void kernel_launch(void* const* d_in, const int* in_sizes, int n_in,
                              void* d_out, int out_size) {
    const float* x      = (const float*)d_in[0];
    // d_in[1] = causal mask, applied analytically
    const float* W_qkv  = (const float*)d_in[2];
    const float* b_qkv  = (const float*)d_in[3];
    const float* W_proj = (const float*)d_in[4];
    const float* b_proj = (const float*)d_in[5];
    float* out = (float*)d_out;

    static int init_done = 0;
    static __half *xh, *wq, *wp, *yh;
    if (!init_done) {
        cudaGetSymbolAddress((void**)&xh, g_xh);
        cudaGetSymbolAddress((void**)&wq, g_wq);
        cudaGetSymbolAddress((void**)&wp, g_wp);
        cudaGetSymbolAddress((void**)&yh, g_yh);
        cudaFuncSetAttribute(mma_gemm_kernel<0>,
                             cudaFuncAttributeMaxDynamicSharedMemorySize,
                             GEMM_SMEM_BYTES);
        cudaFuncSetAttribute(mma_gemm_kernel<1>,
                             cudaFuncAttributeMaxDynamicSharedMemorySize,
                             GEMM_SMEM_BYTES);
        cudaFuncSetAttribute(attn_kernel,
                             cudaFuncAttributeMaxDynamicSharedMemorySize,
                             ATTN_SMEM_BYTES);
        init_done = 1;
    }

    // fused prepass: all fp32 -> fp16 converts in one launch
    convert_all_kernel<<<(N4_TOTAL + 255) / 256, 256>>>(
        x, W_qkv, W_proj, xh, wq, wp);

    // QKV GEMM -> fp16 Q(log2-scaled)/K/V
    mma_gemm_kernel<0><<<dim3(C3_DIM / 128, T_DIM / 64), 128, GEMM_SMEM_BYTES>>>(
        xh, wq, C3_DIM, b_qkv, nullptr);
    // Attention -> fp16 y
    attn_kernel<<<dim3(T_DIM / 128, H_DIM), 256, ATTN_SMEM_BYTES>>>();
    // Projection GEMM -> fp32 out
    mma_gemm_kernel<1><<<dim3(C_DIM / 128, T_DIM / 64), 128, GEMM_SMEM_BYTES>>>(
        yh, wp, C_DIM, b_proj, out);
}

// round 15
// speedup vs baseline: 1.1951x; 1.1352x over previous
#include <cuda_runtime.h>
#include <cuda_fp16.h>
#include <math.h>
#include <stdint.h>

#define T_DIM 4096
#define C_DIM 768
#define H_DIM 12
#define D_DIM 64
#define C3_DIM 2304

// ---------------------------------------------------------------------------
// Global scratch (allocation-free rule). 16B-aligned for uint4/cp.async.
// ---------------------------------------------------------------------------
__device__ __align__(16) __half g_qh[H_DIM * T_DIM * D_DIM];
__device__ __align__(16) __half g_kh[H_DIM * T_DIM * D_DIM];
__device__ __align__(16) __half g_vh[H_DIM * T_DIM * D_DIM];
__device__ __align__(16) __half g_xh[T_DIM * C_DIM];
__device__ __align__(16) __half g_yh[T_DIM * C_DIM];
__device__ __align__(16) __half g_wq[C_DIM * C3_DIM];    // W_qkv fp16 [K][N]
__device__ __align__(16) __half g_wp[C_DIM * C_DIM];     // W_proj fp16 [K][N]

// ---------------------------------------------------------------------------
// PTX helpers (sm_80-level: compile under plain sm_103 target)
// ---------------------------------------------------------------------------
__device__ __forceinline__ uint32_t smem_u32(const void* p) {
    uint32_t a;
    asm("{ .reg .u64 t; cvta.to.shared.u64 t, %1; cvt.u32.u64 %0, t; }"
        : "=r"(a) : "l"(p));
    return a;
}

#define CP16(dst, src) \
    asm volatile("cp.async.cg.shared.global [%0], [%1], 16;" \
                 :: "r"(dst), "l"(src))
#define CP_COMMIT() asm volatile("cp.async.commit_group;" ::: "memory")
#define CP_WAIT0()  asm volatile("cp.async.wait_group 0;" ::: "memory")

#define LDSM_X4(r0, r1, r2, r3, addr) \
    asm volatile("ldmatrix.sync.aligned.m8n8.x4.shared.b16 {%0,%1,%2,%3}, [%4];" \
                 : "=r"(r0), "=r"(r1), "=r"(r2), "=r"(r3) : "r"(addr))

#define LDSM_X4T(r0, r1, r2, r3, addr) \
    asm volatile("ldmatrix.sync.aligned.m8n8.x4.trans.shared.b16 {%0,%1,%2,%3}, [%4];" \
                 : "=r"(r0), "=r"(r1), "=r"(r2), "=r"(r3) : "r"(addr))

#define MMA16816(d, a, b0, b1) \
    asm volatile("mma.sync.aligned.m16n8k16.row.col.f32.f16.f16.f32 " \
                 "{%0,%1,%2,%3}, {%4,%5,%6,%7}, {%8,%9}, {%0,%1,%2,%3};" \
                 : "+f"((d)[0]), "+f"((d)[1]), "+f"((d)[2]), "+f"((d)[3]) \
                 : "r"((a)[0]), "r"((a)[1]), "r"((a)[2]), "r"((a)[3]), \
                   "r"(b0), "r"(b1))

__device__ __forceinline__ uint32_t packh2(float lo, float hi) {
    uint32_t d;
    asm("cvt.rn.f16x2.f32 %0, %1, %2;" : "=r"(d) : "f"(hi), "f"(lo));
    return d;
}
__device__ __forceinline__ uint32_t ex2h2(uint32_t a) {
    uint32_t d;
    asm("ex2.approx.f16x2 %0, %1;" : "=r"(d) : "r"(a));
    return d;
}
__device__ __forceinline__ float ex2(float x) {
    float y;
    asm("ex2.approx.ftz.f32 %0, %1;" : "=f"(y) : "f"(x));
    return y;
}

// ---------------------------------------------------------------------------
// Fused prepass: fp32 -> fp16 for x, W_qkv, W_proj in ONE launch.
// ---------------------------------------------------------------------------
#define N4_X  (T_DIM * C_DIM / 4)
#define N4_WQ (C_DIM * C3_DIM / 4)
#define N4_WP (C_DIM * C_DIM / 4)
#define N4_TOTAL (N4_X + N4_WQ + N4_WP)

__global__ void convert_all_kernel(const float* __restrict__ x,
                                   const float* __restrict__ wq,
                                   const float* __restrict__ wp,
                                   __half* __restrict__ xh,
                                   __half* __restrict__ wqh,
                                   __half* __restrict__ wph) {
    int i = blockIdx.x * blockDim.x + threadIdx.x;
    if (i >= N4_TOTAL) return;
    const float* src;
    __half* dst;
    int j = i;
    if (j < N4_X) { src = x; dst = xh; }
    else if ((j -= N4_X) < N4_WQ) { src = wq; dst = wqh; }
    else { j -= N4_WQ; src = wp; dst = wph; }
    float4 v = ((const float4*)src)[j];
    uint2 o;
    o.x = packh2(v.x, v.y);
    o.y = packh2(v.z, v.w);
    *(uint2*)&dst[4 * (size_t)j] = o;
}

// ---------------------------------------------------------------------------
// fp16 mma GEMM, 2-stage cp.async pipeline. C = A[M,K] @ B[K,N] (B row-major).
// Tile 64x128, BK=64, 128 threads / 4 warps (warp tile 64x32), 4 CTAs/SM.
// MODE 0: qkv scatter (Q pre-scaled by 0.125*log2e). MODE 1: fp32 out.
// ---------------------------------------------------------------------------
#define GA_BUF (64 * 72)                // halves per A stage
#define GB_BUF (64 * 136)               // halves per B stage
#define GA_BUF_B (GA_BUF * 2)
#define GB_BUF_B (GB_BUF * 2)
#define GEMM_SMEM_BYTES (2 * (GA_BUF + GB_BUF) * 2)

#define Q_SCALE 0.18033688011112042f    // 0.125 * log2(e)

template <int MODE>
__global__ __launch_bounds__(128, 4)
void mma_gemm_kernel(const __half* __restrict__ A,
                     const __half* __restrict__ B, int ldb,
                     const float* __restrict__ bias,
                     float* __restrict__ outp) {
    extern __shared__ __half sm[];
    __half (*As)[64][72] = (__half(*)[64][72])sm;
    __half (*Bs)[64][136] = (__half(*)[64][136])(sm + 2 * GA_BUF);

    const int tid = threadIdx.x;
    const int wn = tid >> 5, lane = tid & 31;
    const int g = lane >> 2, qd = lane & 3;
    const int m0 = blockIdx.y * 64;
    const int n0 = blockIdx.x * 128;

    float acc[4][4][4];
    #pragma unroll
    for (int mt = 0; mt < 4; mt++)
        #pragma unroll
        for (int nt = 0; nt < 4; nt++)
            #pragma unroll
            for (int r = 0; r < 4; r++) acc[mt][nt][r] = 0.0f;

    // prologue: stage chunk 0
    #pragma unroll
    for (int i = tid; i < 512; i += 128) {
        const int ra = i >> 3, sga = i & 7;
        CP16(smem_u32(&As[0][ra][sga * 8]),
             &A[(size_t)(m0 + ra) * C_DIM + sga * 8]);
    }
    #pragma unroll
    for (int i = tid; i < 1024; i += 128) {
        const int rb = i >> 4, sgb = i & 15;
        CP16(smem_u32(&Bs[0][rb][sgb * 8]),
             &B[(size_t)rb * ldb + n0 + sgb * 8]);
    }
    CP_COMMIT();

    uint32_t a_base[4];
    #pragma unroll
    for (int mt = 0; mt < 4; mt++)
        a_base[mt] = smem_u32(&As[0][mt * 16 + (lane & 15)][(lane >> 4) * 8]);
    const uint32_t b_base = smem_u32(&Bs[0][lane & 15][wn * 32 + (lane >> 4) * 8]);

    for (int c = 0; c < 12; c++) {
        CP_WAIT0();
        __syncthreads();
        if (c < 11) {
            const int k0 = (c + 1) * 64;
            const int nb = (c + 1) & 1;
            #pragma unroll
            for (int i = tid; i < 512; i += 128) {
                const int ra = i >> 3, sga = i & 7;
                CP16(smem_u32(&As[nb][ra][sga * 8]),
                     &A[(size_t)(m0 + ra) * C_DIM + k0 + sga * 8]);
            }
            #pragma unroll
            for (int i = tid; i < 1024; i += 128) {
                const int rb = i >> 4, sgb = i & 15;
                CP16(smem_u32(&Bs[nb][rb][sgb * 8]),
                     &B[(size_t)(k0 + rb) * ldb + n0 + sgb * 8]);
            }
            CP_COMMIT();
        }
        const uint32_t boffA = (uint32_t)(c & 1) * GA_BUF_B;
        const uint32_t boffB = (uint32_t)(c & 1) * GB_BUF_B;
        #pragma unroll
        for (int kt = 0; kt < 4; kt++) {
            uint32_t af[4][4];
            #pragma unroll
            for (int mt = 0; mt < 4; mt++)
                LDSM_X4(af[mt][0], af[mt][1], af[mt][2], af[mt][3],
                        a_base[mt] + boffA + kt * 32);
            #pragma unroll
            for (int p = 0; p < 2; p++) {
                uint32_t b0, b1, b2, b3;
                LDSM_X4T(b0, b1, b2, b3,
                         b_base + boffB + kt * (16 * 272) + p * 32);
                #pragma unroll
                for (int mt = 0; mt < 4; mt++) {
                    MMA16816(acc[mt][2 * p], af[mt], b0, b1);
                    MMA16816(acc[mt][2 * p + 1], af[mt], b2, b3);
                }
            }
        }
    }

    // epilogue
    #pragma unroll
    for (int nt = 0; nt < 4; nt++) {
        const int f = n0 + wn * 32 + nt * 8 + qd * 2;
        const float b0v = bias[f], b1v = bias[f + 1];
        if (MODE == 0) {
            const int sec = f / C_DIM;
            const int cc = f - sec * C_DIM;
            const int hh = cc >> 6, d = cc & 63;
            const float sc = (sec == 0) ? Q_SCALE : 1.0f;
            __half* dst = (sec == 0) ? g_qh : (sec == 1) ? g_kh : g_vh;
            #pragma unroll
            for (int mt = 0; mt < 4; mt++) {
                const int m = m0 + mt * 16 + g;
                *(uint32_t*)&dst[((size_t)hh * T_DIM + m) * D_DIM + d] =
                    packh2((acc[mt][nt][0] + b0v) * sc, (acc[mt][nt][1] + b1v) * sc);
                *(uint32_t*)&dst[((size_t)hh * T_DIM + m + 8) * D_DIM + d] =
                    packh2((acc[mt][nt][2] + b0v) * sc, (acc[mt][nt][3] + b1v) * sc);
            }
        } else {
            #pragma unroll
            for (int mt = 0; mt < 4; mt++) {
                const int m = m0 + mt * 16 + g;
                float2 r0 = make_float2(acc[mt][nt][0] + b0v, acc[mt][nt][1] + b1v);
                float2 r1 = make_float2(acc[mt][nt][2] + b0v, acc[mt][nt][3] + b1v);
                *(float2*)&outp[(size_t)m * C_DIM + f] = r0;
                *(float2*)&outp[(size_t)(m + 8) * C_DIM + f] = r1;
            }
        }
    }
}

// ---------------------------------------------------------------------------
// Causal flash attention, fp16 mma, 2-stage cp.async K/V pipeline.
// CTA: 64 q-rows, 4 warps (16 rows each), 128 threads, 4 CTAs/SM.
// 1D grid, globally heavy-first: b -> qb = 63 - b/12, h = b%12.
// Softmax log2-domain; f32 subtract, f16x2 ex2 -> P fragments; row-sum l via
// ones-column MMA; conditional O/l rescale.
// ---------------------------------------------------------------------------
#define KV_BUF (64 * 72)
#define KV_BUF_B (KV_BUF * 2)
#define ATTN_SMEM_BYTES ((64 * 72 + 4 * KV_BUF) * 2)
#define ONES_H2 0x3C003C00u             // (1.0h, 1.0h)

__global__ __launch_bounds__(128, 4)
void attn_kernel() {
    extern __shared__ __half sm[];
    __half (*Qs)[72] = (__half(*)[72])sm;                      // [64][72]
    __half (*Ks)[64][72] = (__half(*)[64][72])(sm + 64 * 72);
    __half (*Vs)[64][72] = (__half(*)[64][72])(sm + 64 * 72 + 2 * KV_BUF);

    const int b = blockIdx.x;
    const int qb = 63 - b / 12;          // heavy q-tiles first, all heads
    const int h = b % 12;
    const int tid = threadIdx.x;
    const int w = tid >> 5, lane = tid & 31;
    const int g = lane >> 2, qd = lane & 3;

    // stage Q + K/V block 0 as one async group
    const __half* Qg = g_qh + ((size_t)h * T_DIM + qb * 64) * D_DIM;
    #pragma unroll
    for (int i = tid; i < 512; i += 128) {
        const int r = i >> 3, sg = i & 7;
        CP16(smem_u32(&Qs[r][sg * 8]), &Qg[r * D_DIM + sg * 8]);
    }
    {
        const __half* Kg = g_kh + ((size_t)h * T_DIM) * D_DIM;
        const __half* Vg = g_vh + ((size_t)h * T_DIM) * D_DIM;
        #pragma unroll
        for (int i = tid; i < 512; i += 128) {
            const int r = i >> 3, sg = i & 7;
            CP16(smem_u32(&Ks[0][r][sg * 8]), &Kg[r * D_DIM + sg * 8]);
            CP16(smem_u32(&Vs[0][r][sg * 8]), &Vg[r * D_DIM + sg * 8]);
        }
    }
    CP_COMMIT();

    uint32_t qf[4][4];
    float o[8][4];
    float lsum[4] = {0.0f, 0.0f, 0.0f, 0.0f};
    #pragma unroll
    for (int nt = 0; nt < 8; nt++)
        #pragma unroll
        for (int r = 0; r < 4; r++) o[nt][r] = 0.0f;
    float m0r = -1e30f, m1r = -1e30f;

    const int row0 = qb * 64 + w * 16 + g;
    const int row1 = row0 + 8;

    const uint32_t k_base = smem_u32(&Ks[0][(lane >> 4) * 8 + (lane & 7)][((lane >> 3) & 1) * 8]);
    const uint32_t v_base = smem_u32(&Vs[0][lane & 15][(lane >> 4) * 8]);

    const int jend = qb;                 // key blocks 0..qb (inclusive)
    for (int jb = 0; jb <= jend; jb++) {
        CP_WAIT0();
        __syncthreads();
        if (jb == 0) {
            const uint32_t qa = smem_u32(&Qs[w * 16 + (lane & 15)][(lane >> 4) * 8]);
            #pragma unroll
            for (int kt = 0; kt < 4; kt++)
                LDSM_X4(qf[kt][0], qf[kt][1], qf[kt][2], qf[kt][3], qa + kt * 32);
        }
        if (jb < jend) {
            const int nb = (jb + 1) & 1;
            const __half* Kg = g_kh + ((size_t)h * T_DIM + (jb + 1) * 64) * D_DIM;
            const __half* Vg = g_vh + ((size_t)h * T_DIM + (jb + 1) * 64) * D_DIM;
            #pragma unroll
            for (int i = tid; i < 512; i += 128) {
                const int r = i >> 3, sg = i & 7;
                CP16(smem_u32(&Ks[nb][r][sg * 8]), &Kg[r * D_DIM + sg * 8]);
                CP16(smem_u32(&Vs[nb][r][sg * 8]), &Vg[r * D_DIM + sg * 8]);
            }
            CP_COMMIT();
        }
        const uint32_t boff = (uint32_t)(jb & 1) * KV_BUF_B;

        // ---- S = Q K^T (log2-domain scores) ----
        float s[8][4];
        #pragma unroll
        for (int nt = 0; nt < 8; nt++)
            #pragma unroll
            for (int r = 0; r < 4; r++) s[nt][r] = 0.0f;

        #pragma unroll
        for (int kt = 0; kt < 4; kt++) {
            #pragma unroll
            for (int p = 0; p < 4; p++) {
                uint32_t b0, b1, b2, b3;
                LDSM_X4(b0, b1, b2, b3, k_base + boff + p * 16 * 144 + kt * 32);
                MMA16816(s[2 * p], qf[kt], b0, b1);
                MMA16816(s[2 * p + 1], qf[kt], b2, b3);
            }
        }

        // ---- causal mask (only the diagonal block clips) ----
        if (jb == qb) {
            #pragma unroll
            for (int nt = 0; nt < 8; nt++) {
                const int cb = jb * 64 + nt * 8 + qd * 2;
                if (cb > row0)     s[nt][0] = -1e30f;
                if (cb + 1 > row0) s[nt][1] = -1e30f;
                if (cb > row1)     s[nt][2] = -1e30f;
                if (cb + 1 > row1) s[nt][3] = -1e30f;
            }
        }

        // ---- row max (f32, quad shuffles) ----
        float bm0 = s[0][0], bm1 = s[0][2];
        #pragma unroll
        for (int nt = 0; nt < 8; nt++) {
            bm0 = fmaxf(bm0, fmaxf(s[nt][0], s[nt][1]));
            bm1 = fmaxf(bm1, fmaxf(s[nt][2], s[nt][3]));
        }
        bm0 = fmaxf(bm0, __shfl_xor_sync(0xffffffffu, bm0, 1));
        bm0 = fmaxf(bm0, __shfl_xor_sync(0xffffffffu, bm0, 2));
        bm1 = fmaxf(bm1, __shfl_xor_sync(0xffffffffu, bm1, 1));
        bm1 = fmaxf(bm1, __shfl_xor_sync(0xffffffffu, bm1, 2));

        // ---- rescale only when the running max actually moved ----
        if (__any_sync(0xffffffffu, (bm0 > m0r) | (bm1 > m1r))) {
            const float mn0 = fmaxf(m0r, bm0), mn1 = fmaxf(m1r, bm1);
            const float cr0 = ex2(m0r - mn0), cr1 = ex2(m1r - mn1);
            m0r = mn0; m1r = mn1;
            #pragma unroll
            for (int nt = 0; nt < 8; nt++) {
                o[nt][0] *= cr0; o[nt][1] *= cr0;
                o[nt][2] *= cr1; o[nt][3] *= cr1;
            }
            lsum[0] *= cr0; lsum[1] *= cr0;
            lsum[2] *= cr1; lsum[3] *= cr1;
        }

        // ---- P fragments: f32 subtract (exact), pack, MUFU ex2.f16x2 ----
        const float mn0 = m0r, mn1 = m1r;
        uint32_t pf[4][4];
        #pragma unroll
        for (int kt = 0; kt < 4; kt++) {
            pf[kt][0] = ex2h2(packh2(s[2 * kt][0] - mn0,     s[2 * kt][1] - mn0));
            pf[kt][1] = ex2h2(packh2(s[2 * kt][2] - mn1,     s[2 * kt][3] - mn1));
            pf[kt][2] = ex2h2(packh2(s[2 * kt + 1][0] - mn0, s[2 * kt + 1][1] - mn0));
            pf[kt][3] = ex2h2(packh2(s[2 * kt + 1][2] - mn1, s[2 * kt + 1][3] - mn1));
        }

        // ---- O += P V, and l += P ones ----
        #pragma unroll
        for (int kt = 0; kt < 4; kt++) {
            MMA16816(lsum, pf[kt], ONES_H2, ONES_H2);
            #pragma unroll
            for (int dt = 0; dt < 4; dt++) {
                uint32_t v0, v1, v2, v3;
                LDSM_X4T(v0, v1, v2, v3, v_base + boff + kt * 16 * 144 + dt * 32);
                MMA16816(o[2 * dt], pf[kt], v0, v1);
                MMA16816(o[2 * dt + 1], pf[kt], v2, v3);
            }
        }
    }

    // epilogue: normalize, write y fp16 [T][C]
    const float il0 = 1.0f / lsum[0], il1 = 1.0f / lsum[2];
    __half* y0 = g_yh + (size_t)row0 * C_DIM + h * D_DIM;
    __half* y1 = g_yh + (size_t)row1 * C_DIM + h * D_DIM;
    #pragma unroll
    for (int nt = 0; nt < 8; nt++) {
        const int d = nt * 8 + qd * 2;
        *(uint32_t*)&y0[d] = packh2(o[nt][0] * il0, o[nt][1] * il0);
        *(uint32_t*)&y1[d] = packh2(o[nt][2] * il1, o[nt][3] * il1);
    }
}

// ---------------------------------------------------------------------------
extern "C" void kernel_launch(void* const* d_in, const int* in_sizes, int n_in,
                              void* d_out, int out_size) {
    const float* x      = (const float*)d_in[0];
    // d_in[1] = causal mask, applied analytically
    const float* W_qkv  = (const float*)d_in[2];
    const float* b_qkv  = (const float*)d_in[3];
    const float* W_proj = (const float*)d_in[4];
    const float* b_proj = (const float*)d_in[5];
    float* out = (float*)d_out;

    static int init_done = 0;
    static __half *xh, *wq, *wp, *yh;
    if (!init_done) {
        cudaGetSymbolAddress((void**)&xh, g_xh);
        cudaGetSymbolAddress((void**)&wq, g_wq);
        cudaGetSymbolAddress((void**)&wp, g_wp);
        cudaGetSymbolAddress((void**)&yh, g_yh);
        cudaFuncSetAttribute(mma_gemm_kernel<0>,
                             cudaFuncAttributeMaxDynamicSharedMemorySize,
                             GEMM_SMEM_BYTES);
        cudaFuncSetAttribute(mma_gemm_kernel<1>,
                             cudaFuncAttributeMaxDynamicSharedMemorySize,
                             GEMM_SMEM_BYTES);
        cudaFuncSetAttribute(attn_kernel,
                             cudaFuncAttributeMaxDynamicSharedMemorySize,
                             ATTN_SMEM_BYTES);
        init_done = 1;
    }

    // fused prepass: all fp32 -> fp16 converts in one launch
    convert_all_kernel<<<(N4_TOTAL + 255) / 256, 256>>>(
        x, W_qkv, W_proj, xh, wq, wp);

    // QKV GEMM -> fp16 Q(log2-scaled)/K/V
    mma_gemm_kernel<0><<<dim3(C3_DIM / 128, T_DIM / 64), 128, GEMM_SMEM_BYTES>>>(
        xh, wq, C3_DIM, b_qkv, nullptr);
    // Attention -> fp16 y (1D grid, globally heavy-first)
    attn_kernel<<<(T_DIM / 64) * H_DIM, 128, ATTN_SMEM_BYTES>>>();
    // Projection GEMM -> fp32 out
    mma_gemm_kernel<1><<<dim3(C_DIM / 128, T_DIM / 64), 128, GEMM_SMEM_BYTES>>>(
        yh, wp, C_DIM, b_proj, out);
}